// round 13
// baseline (speedup 1.0000x reference)
#include <cuda_runtime.h>
#include <cuda_fp16.h>

#define NN 100000
#define NE 3200000
#define FULLMASK 0xffffffffu

// ---------------- device scratch ----------------
__device__ int g_cnt[NN];
__device__ int g_rs[NN + 1];
__device__ int g_cur[NN];
__device__ int g_csr[NE];
__device__ int g_bsum[32];
__device__ int g_flag[1];
__device__ unsigned g_almax1[8];
__device__ unsigned g_almax2[8];
__device__ __align__(16) __half g_h1h[(size_t)NN * 128];
__device__ __align__(16) __half g_hAh[(size_t)NN * 128];
__device__ __align__(16) float g_hA[(size_t)NN * 128];
__device__ __align__(16) float g_al1[NN * 8];
__device__ __align__(16) float g_ar1[NN * 8];
__device__ __align__(16) float g_al2[NN * 8];
__device__ __align__(16) float g_ar2[NN * 8];
__device__ __align__(16) float g_wsrc[128 * 8];
__device__ __align__(16) float g_wdst[128 * 8];
__device__ __align__(16) float g_W1h[128 * 128];
__device__ __align__(16) float g_W1l[128 * 128];
__device__ __align__(16) float g_Wb_hi[1024 * 40];
__device__ __align__(16) float g_Wb_lo[1024 * 40];
__device__ __align__(16) __half g_aggh[(size_t)NN * 1024];

// ---------------- helpers ----------------
__device__ __forceinline__ unsigned fkey(float f) {
    unsigned u = __float_as_uint(f);
    return (u & 0x80000000u) ? ~u : (u | 0x80000000u);
}
__device__ __forceinline__ float funkey2(unsigned k) {
    unsigned u = (k & 0x80000000u) ? (k ^ 0x80000000u) : ~k;
    return __uint_as_float(u);
}
__device__ __forceinline__ float lrelu(float e) { return fmaxf(e, 0.2f * e); }

__device__ __forceinline__ unsigned f2tf(float x) {
    unsigned r;
    asm("cvt.rna.tf32.f32 %0, %1;" : "=r"(r) : "f"(x));
    return r;
}

__device__ __forceinline__ void mma_tf32(float* d, const unsigned* a, unsigned b0, unsigned b1) {
    asm volatile(
        "mma.sync.aligned.m16n8k8.row.col.f32.tf32.tf32.f32 "
        "{%0,%1,%2,%3}, {%4,%5,%6,%7}, {%8,%9}, {%0,%1,%2,%3};\n"
        : "+f"(d[0]), "+f"(d[1]), "+f"(d[2]), "+f"(d[3])
        : "r"(a[0]), "r"(a[1]), "r"(a[2]), "r"(a[3]), "r"(b0), "r"(b1));
}

__device__ __forceinline__ float4 h2f4(uint2 v) {
    __half2 a = *(__half2*)&v.x;
    __half2 b = *(__half2*)&v.y;
    float2 fa = __half22float2(a);
    float2 fb = __half22float2(b);
    return make_float4(fa.x, fa.y, fb.x, fb.y);
}
__device__ __forceinline__ uint2 f4h2(float4 o) {
    uint2 v;
    *(__half2*)&v.x = __float22half2_rn(make_float2(o.x, o.y));
    *(__half2*)&v.y = __float22half2_rn(make_float2(o.z, o.w));
    return v;
}

// ---------------- init ----------------
__global__ void k_init(const long long* ei) {
    int t = threadIdx.x;
    int gid = blockIdx.x * blockDim.x + t;
    for (int i = gid; i < NN; i += gridDim.x * blockDim.x) g_cnt[i] = 0;
    if (blockIdx.x == 0) {
        __shared__ int sbad;
        if (t == 0) sbad = 0;
        __syncthreads();
        int bad = 0;
        for (int i = t; i < 4096; i += blockDim.x) {
            long long v = ei[i];
            if (v < 0 || v >= NN) bad = 1;
        }
        if (bad) atomicOr(&sbad, 1);
        __syncthreads();
        if (t == 0) g_flag[0] = sbad;
        if (t < 8) {
            g_almax1[t] = 0u;
            g_almax2[t] = 0u;
        }
    }
}

// ---------------- histogram of in-degrees (4 edges / thread) ----------------
__global__ void k_hist(const void* ei) {
    int base = (blockIdx.x * blockDim.x + threadIdx.x) * 4;
    if (base >= NE) return;
    int i32 = g_flag[0];
    int d0, d1, d2, d3;
    if (i32) {
        int4 dv = *(const int4*)((const int*)ei + NE + base);
        d0 = dv.x; d1 = dv.y; d2 = dv.z; d3 = dv.w;
    } else {
        const longlong2* p = (const longlong2*)((const long long*)ei + NE + base);
        longlong2 a = p[0], b = p[1];
        d0 = (int)a.x; d1 = (int)a.y; d2 = (int)b.x; d3 = (int)b.y;
    }
    atomicAdd(&g_cnt[d0], 1);
    atomicAdd(&g_cnt[d1], 1);
    atomicAdd(&g_cnt[d2], 1);
    atomicAdd(&g_cnt[d3], 1);
}

// ---------------- coalesced 3-kernel exclusive scan (chunk = 4096) ----------------
__global__ void k_scan1() {
    __shared__ int sw[32];
    int b = blockIdx.x, t = threadIdx.x;
    int base = b * 4096 + t * 4;
    int s = 0;
#pragma unroll
    for (int j = 0; j < 4; j++) {
        int idx = base + j;
        s += (idx < NN) ? g_cnt[idx] : 0;
    }
#pragma unroll
    for (int o = 16; o; o >>= 1) s += __shfl_xor_sync(FULLMASK, s, o);
    if ((t & 31) == 0) sw[t >> 5] = s;
    __syncthreads();
    if (t < 32) {
        int v = sw[t];
#pragma unroll
        for (int o = 16; o; o >>= 1) v += __shfl_xor_sync(FULLMASK, v, o);
        if (t == 0) g_bsum[b] = v;
    }
}

__global__ void k_scan2(int nb) {
    int t = threadIdx.x;
    int v = (t < nb) ? g_bsum[t] : 0;
    int orig = v;
#pragma unroll
    for (int o = 1; o < 32; o <<= 1) {
        int y = __shfl_up_sync(FULLMASK, v, o);
        if (t >= o) v += y;
    }
    if (t < nb) g_bsum[t] = v - orig;
}

__global__ void k_scan3() {
    __shared__ int sw[32];
    int b = blockIdx.x, t = threadIdx.x;
    int lane = t & 31, w = t >> 5;
    int base = b * 4096 + t * 4;
    int v[4];
#pragma unroll
    for (int j = 0; j < 4; j++) {
        int idx = base + j;
        v[j] = (idx < NN) ? g_cnt[idx] : 0;
    }
    int tl = v[0] + v[1] + v[2] + v[3];
    int x = tl;
#pragma unroll
    for (int o = 1; o < 32; o <<= 1) {
        int y = __shfl_up_sync(FULLMASK, x, o);
        if (lane >= o) x += y;
    }
    if (lane == 31) sw[w] = x;
    __syncthreads();
    if (w == 0) {
        int z = sw[lane];
#pragma unroll
        for (int o = 1; o < 32; o <<= 1) {
            int y = __shfl_up_sync(FULLMASK, z, o);
            if (lane >= o) z += y;
        }
        sw[lane] = z;
    }
    __syncthreads();
    int woff = (w > 0) ? sw[w - 1] : 0;
    int run = g_bsum[b] + woff + (x - tl);
#pragma unroll
    for (int j = 0; j < 4; j++) {
        int idx = base + j;
        if (idx <= NN) {
            g_rs[idx] = run;
            if (idx < NN) g_cur[idx] = run;
        }
        run += v[j];
    }
}

// ---------------- CSR fill (4 edges / thread) ----------------
__global__ void k_fill(const void* ei) {
    int base = (blockIdx.x * blockDim.x + threadIdx.x) * 4;
    if (base >= NE) return;
    int i32 = g_flag[0];
    int s0, s1, s2, s3, d0, d1, d2, d3;
    if (i32) {
        int4 sv = *(const int4*)((const int*)ei + base);
        int4 dv = *(const int4*)((const int*)ei + NE + base);
        s0 = sv.x; s1 = sv.y; s2 = sv.z; s3 = sv.w;
        d0 = dv.x; d1 = dv.y; d2 = dv.z; d3 = dv.w;
    } else {
        const longlong2* ps = (const longlong2*)((const long long*)ei + base);
        const longlong2* pd = (const longlong2*)((const long long*)ei + NE + base);
        longlong2 a = ps[0], b = ps[1];
        longlong2 c = pd[0], e = pd[1];
        s0 = (int)a.x; s1 = (int)a.y; s2 = (int)b.x; s3 = (int)b.y;
        d0 = (int)c.x; d1 = (int)c.y; d2 = (int)e.x; d3 = (int)e.y;
    }
    int p0 = atomicAdd(&g_cur[d0], 1);
    int p1 = atomicAdd(&g_cur[d1], 1);
    int p2 = atomicAdd(&g_cur[d2], 1);
    int p3 = atomicAdd(&g_cur[d3], 1);
    g_csr[p0] = s0;
    g_csr[p1] = s1;
    g_csr[p2] = s2;
    g_csr[p3] = s3;
}

// ---------------- weight prep ----------------
__global__ void k_prep_eff(const float* __restrict__ W2, const float* __restrict__ as2,
                           const float* __restrict__ ad2) {
    int t = blockIdx.x * blockDim.x + threadIdx.x;
    if (t >= 1024) return;
    int k = t >> 3, h = t & 7;
    float s = 0.f, d = 0.f;
    for (int c = 0; c < 40; c++) {
        float w = W2[k * 320 + h * 40 + c];
        s += w * as2[h * 40 + c];
        d += w * ad2[h * 40 + c];
    }
    g_wsrc[t] = s;
    g_wdst[t] = d;
}

__global__ void k_prep_wbig(const float* __restrict__ W2) {
    int t = blockIdx.x * blockDim.x + threadIdx.x;
    if (t >= 40960) return;
    int i = t / 40, c = t % 40;
    int h = i >> 7, k = i & 127;
    float wv = W2[k * 320 + h * 40 + c] * 0.125f;
    float hif = __uint_as_float(f2tf(wv));
    g_Wb_hi[t] = hif;
    g_Wb_lo[t] = __uint_as_float(f2tf(wv - hif));
}

__global__ void k_prep_w1(const float* __restrict__ W1) {
    int t = blockIdx.x * blockDim.x + threadIdx.x;
    if (t >= 16384) return;
    float v = W1[t];
    float hif = __uint_as_float(f2tf(v));
    g_W1h[t] = hif;
    g_W1l[t] = __uint_as_float(f2tf(v - hif));
}

// ---------------- GEMM1 (3xTF32 MMA): h1h = x @ W1, smem-staged coalesced epilogue,
//                  fused alpha1 (fp32 fragment domain) + global almax1 ----------------
__global__ __launch_bounds__(128) void k_gemm1_tc(const float* __restrict__ x,
                                                  const float* __restrict__ as1,
                                                  const float* __restrict__ ad1) {
    __shared__ float As[64][36];
    __shared__ union {
        struct {
            float Wh[32][132];
            float Wl[32][132];
        } w;
        __half Hs[64][144];
    } U;
    __shared__ unsigned salmax[8];
    int t = threadIdx.x;
    int lane = t & 31, w = t >> 5;
    int g = lane >> 2, tg = lane & 3;
    int n0 = blockIdx.x * 64;
    if (t < 8) salmax[t] = 0u;

    float acc[16][4];
#pragma unroll
    for (int nt = 0; nt < 16; nt++)
#pragma unroll
        for (int i = 0; i < 4; i++) acc[nt][i] = 0.f;

    for (int k0 = 0; k0 < 128; k0 += 32) {
#pragma unroll
        for (int i = 0; i < 4; i++) {
            int f = t + i * 128;
            int r = f >> 3, c4 = f & 7;
            int nn = n0 + r;
            if (nn >= NN) nn = NN - 1;
            float4 v = *(const float4*)&x[(size_t)nn * 128 + k0 + c4 * 4];
            *(float4*)&As[r][c4 * 4] = v;
        }
#pragma unroll
        for (int i = 0; i < 8; i++) {
            int f = t + i * 128;
            int kr = f >> 5, c4 = f & 31;
            *(float4*)&U.w.Wh[kr][c4 * 4] = *(const float4*)&g_W1h[(size_t)(k0 + kr) * 128 + c4 * 4];
            *(float4*)&U.w.Wl[kr][c4 * 4] = *(const float4*)&g_W1l[(size_t)(k0 + kr) * 128 + c4 * 4];
        }
        __syncthreads();
#pragma unroll
        for (int k8 = 0; k8 < 4; k8++) {
            float a0 = As[w * 16 + g][k8 * 8 + tg];
            float a1 = As[w * 16 + g + 8][k8 * 8 + tg];
            float a2 = As[w * 16 + g][k8 * 8 + tg + 4];
            float a3 = As[w * 16 + g + 8][k8 * 8 + tg + 4];
            unsigned ah[4], al[4];
            ah[0] = f2tf(a0);
            ah[1] = f2tf(a1);
            ah[2] = f2tf(a2);
            ah[3] = f2tf(a3);
            al[0] = f2tf(a0 - __uint_as_float(ah[0]));
            al[1] = f2tf(a1 - __uint_as_float(ah[1]));
            al[2] = f2tf(a2 - __uint_as_float(ah[2]));
            al[3] = f2tf(a3 - __uint_as_float(ah[3]));
#pragma unroll
            for (int nt = 0; nt < 16; nt++) {
                unsigned bh0 = __float_as_uint(U.w.Wh[k8 * 8 + tg][nt * 8 + g]);
                unsigned bh1 = __float_as_uint(U.w.Wh[k8 * 8 + tg + 4][nt * 8 + g]);
                unsigned bl0 = __float_as_uint(U.w.Wl[k8 * 8 + tg][nt * 8 + g]);
                unsigned bl1 = __float_as_uint(U.w.Wl[k8 * 8 + tg + 4][nt * 8 + g]);
                mma_tf32(acc[nt], ah, bh0, bh1);
                mma_tf32(acc[nt], ah, bl0, bl1);
                mma_tf32(acc[nt], al, bh0, bh1);
            }
        }
        __syncthreads();
    }

#pragma unroll
    for (int nt = 0; nt < 16; nt++) {
        int col = nt * 8 + 2 * tg;
        *(__half2*)&U.Hs[w * 16 + g][col] = __float22half2_rn(make_float2(acc[nt][0], acc[nt][1]));
        *(__half2*)&U.Hs[w * 16 + g + 8][col] = __float22half2_rn(make_float2(acc[nt][2], acc[nt][3]));
    }

    int r0 = n0 + w * 16 + g;
    int r1 = r0 + 8;
#pragma unroll
    for (int h = 0; h < 8; h++) {
        float s0 = 0.f, d0 = 0.f, s1 = 0.f, d1 = 0.f;
#pragma unroll
        for (int q = 0; q < 2; q++) {
            int nt = 2 * h + q;
            int col = nt * 8 + 2 * tg;
            float wa0 = as1[col], wa1 = as1[col + 1];
            float wd0 = ad1[col], wd1 = ad1[col + 1];
            s0 += acc[nt][0] * wa0 + acc[nt][1] * wa1;
            d0 += acc[nt][0] * wd0 + acc[nt][1] * wd1;
            s1 += acc[nt][2] * wa0 + acc[nt][3] * wa1;
            d1 += acc[nt][2] * wd0 + acc[nt][3] * wd1;
        }
        s0 += __shfl_xor_sync(FULLMASK, s0, 1);
        s0 += __shfl_xor_sync(FULLMASK, s0, 2);
        d0 += __shfl_xor_sync(FULLMASK, d0, 1);
        d0 += __shfl_xor_sync(FULLMASK, d0, 2);
        s1 += __shfl_xor_sync(FULLMASK, s1, 1);
        s1 += __shfl_xor_sync(FULLMASK, s1, 2);
        d1 += __shfl_xor_sync(FULLMASK, d1, 1);
        d1 += __shfl_xor_sync(FULLMASK, d1, 2);
        if (tg == 0) {
            if (r0 < NN) {
                g_al1[r0 * 8 + h] = s0;
                g_ar1[r0 * 8 + h] = d0;
                atomicMax(&salmax[h], fkey(s0));
            }
            if (r1 < NN) {
                g_al1[r1 * 8 + h] = s1;
                g_ar1[r1 * 8 + h] = d1;
                atomicMax(&salmax[h], fkey(s1));
            }
        }
    }
    __syncthreads();

    {
        int r = t >> 1;
        int row = n0 + r;
        int ch = (t & 1) * 64;
        if (row < NN) {
            uint4 buf[8];
#pragma unroll
            for (int i = 0; i < 8; i++) buf[i] = *(uint4*)&U.Hs[r][ch + i * 8];
#pragma unroll
            for (int i = 0; i < 8; i++) *(uint4*)&g_h1h[(size_t)row * 128 + ch + i * 8] = buf[i];
        }
    }
    if (t < 8) atomicMax(&g_almax1[t], salmax[t]);
}

// ---------------- edge1: warp/dst, unroll-4, half gather rows ----------------
__global__ __launch_bounds__(256) void k_edge1(const float* __restrict__ b1) {
    int gw = (blockIdx.x * blockDim.x + threadIdx.x) >> 5;
    int lane = threadIdx.x & 31;
    if (gw >= NN) return;
    int n = gw;
    int beg = g_rs[n], deg = g_rs[n + 1] - beg;
    int head = lane >> 2;
    float ar_h = g_ar1[n * 8 + head];
    float m = lrelu(funkey2(g_almax1[head]) + ar_h);

    float4 acc = make_float4(0.f, 0.f, 0.f, 0.f);
    float den = 0.f;
    const uint2* hp = (const uint2*)g_h1h;
    const int* cp = g_csr + beg;
    int j = 0;
    for (; j + 3 < deg; j += 4) {
        int s0 = cp[j], s1 = cp[j + 1], s2 = cp[j + 2], s3 = cp[j + 3];
        float a0 = g_al1[s0 * 8 + head];
        float a1 = g_al1[s1 * 8 + head];
        float a2 = g_al1[s2 * 8 + head];
        float a3 = g_al1[s3 * 8 + head];
        uint2 r0 = hp[(size_t)s0 * 32 + lane];
        uint2 r1 = hp[(size_t)s1 * 32 + lane];
        uint2 r2 = hp[(size_t)s2 * 32 + lane];
        uint2 r3 = hp[(size_t)s3 * 32 + lane];
        float p0 = __expf(lrelu(a0 + ar_h) - m);
        float p1 = __expf(lrelu(a1 + ar_h) - m);
        float p2 = __expf(lrelu(a2 + ar_h) - m);
        float p3 = __expf(lrelu(a3 + ar_h) - m);
        float4 h0 = h2f4(r0), h1v = h2f4(r1), h2v = h2f4(r2), h3v = h2f4(r3);
        den += (p0 + p1) + (p2 + p3);
        acc.x += p0 * h0.x + p1 * h1v.x + p2 * h2v.x + p3 * h3v.x;
        acc.y += p0 * h0.y + p1 * h1v.y + p2 * h2v.y + p3 * h3v.y;
        acc.z += p0 * h0.z + p1 * h1v.z + p2 * h2v.z + p3 * h3v.z;
        acc.w += p0 * h0.w + p1 * h1v.w + p2 * h2v.w + p3 * h3v.w;
    }
    for (; j < deg; j++) {
        int s0 = cp[j];
        float p0 = __expf(lrelu(g_al1[s0 * 8 + head] + ar_h) - m);
        float4 h0 = h2f4(hp[(size_t)s0 * 32 + lane]);
        den += p0;
        acc.x += p0 * h0.x;
        acc.y += p0 * h0.y;
        acc.z += p0 * h0.z;
        acc.w += p0 * h0.w;
    }
    float inv = (deg > 0) ? 1.0f / den : 0.0f;
    float4 bb = ((const float4*)b1)[lane];
    float4 o;
    o.x = acc.x * inv + bb.x;
    o.y = acc.y * inv + bb.y;
    o.z = acc.z * inv + bb.z;
    o.w = acc.w * inv + bb.w;
    o.x = o.x > 0.f ? o.x : (__expf(o.x) - 1.f);
    o.y = o.y > 0.f ? o.y : (__expf(o.y) - 1.f);
    o.z = o.z > 0.f ? o.z : (__expf(o.z) - 1.f);
    o.w = o.w > 0.f ? o.w : (__expf(o.w) - 1.f);
    ((float4*)g_hA)[(size_t)n * 32 + lane] = o;
    ((uint2*)g_hAh)[(size_t)n * 32 + lane] = f4h2(o);
}

// ---------------- alpha2 + almax2 tracking (separate, streaming, fp32) ----------------
__global__ __launch_bounds__(256) void k_alpha2() {
    __shared__ unsigned smax[8];
    int t = threadIdx.x;
    if (t < 8) smax[t] = 0u;
    __syncthreads();
    int wid = (blockIdx.x * blockDim.x + t) >> 5;
    int lane = t & 31;
    int nwarp = (gridDim.x * blockDim.x) >> 5;
    float ws[4][8], wd[4][8];
#pragma unroll
    for (int j = 0; j < 4; j++) {
        int k = lane * 4 + j;
#pragma unroll
        for (int h = 0; h < 8; h++) {
            ws[j][h] = g_wsrc[k * 8 + h];
            wd[j][h] = g_wdst[k * 8 + h];
        }
    }
    float lmax[8];
#pragma unroll
    for (int h = 0; h < 8; h++) lmax[h] = -1e30f;
    for (int n = wid; n < NN; n += nwarp) {
        float4 hv = ((const float4*)g_hA)[(size_t)n * 32 + lane];
        float hvv[4] = {hv.x, hv.y, hv.z, hv.w};
        float as[8], ad[8];
#pragma unroll
        for (int h = 0; h < 8; h++) {
            as[h] = 0.f;
            ad[h] = 0.f;
        }
#pragma unroll
        for (int j = 0; j < 4; j++)
#pragma unroll
            for (int h = 0; h < 8; h++) {
                as[h] += hvv[j] * ws[j][h];
                ad[h] += hvv[j] * wd[j][h];
            }
#pragma unroll
        for (int h = 0; h < 8; h++) {
#pragma unroll
            for (int o = 16; o; o >>= 1) {
                as[h] += __shfl_xor_sync(FULLMASK, as[h], o);
                ad[h] += __shfl_xor_sync(FULLMASK, ad[h], o);
            }
        }
        if (lane == 0) {
#pragma unroll
            for (int h = 0; h < 8; h++) {
                g_al2[n * 8 + h] = as[h];
                g_ar2[n * 8 + h] = ad[h];
                lmax[h] = fmaxf(lmax[h], as[h]);
            }
        }
    }
    if (lane == 0) {
#pragma unroll
        for (int h = 0; h < 8; h++) atomicMax(&smax[h], fkey(lmax[h]));
    }
    __syncthreads();
    if (t < 8) atomicMax(&g_almax2[t], smax[t]);
}

// ---------------- edge2: warp/dst, unroll-2, half gather rows, fp16 agg out ----------------
__global__ __launch_bounds__(256) void k_edge2() {
    int gw = (blockIdx.x * blockDim.x + threadIdx.x) >> 5;
    int lane = threadIdx.x & 31;
    if (gw >= NN) return;
    int n = gw;
    int beg = g_rs[n], deg = g_rs[n + 1] - beg;
    int hsel = lane & 7;
    float ar_o = g_ar2[n * 8 + hsel];
    float m = lrelu(funkey2(g_almax2[hsel]) + ar_o);

    float4 acc[8];
#pragma unroll
    for (int h = 0; h < 8; h++) acc[h] = make_float4(0.f, 0.f, 0.f, 0.f);
    float den = 0.f;
    const uint2* hp = (const uint2*)g_hAh;
    const int* cp = g_csr + beg;
    int j = 0;
    for (; j + 1 < deg; j += 2) {
        int s0 = cp[j], s1 = cp[j + 1];
        float a0 = g_al2[s0 * 8 + hsel];
        float a1 = g_al2[s1 * 8 + hsel];
        uint2 r0 = hp[(size_t)s0 * 32 + lane];
        uint2 r1 = hp[(size_t)s1 * 32 + lane];
        float p0 = __expf(lrelu(a0 + ar_o) - m);
        float p1 = __expf(lrelu(a1 + ar_o) - m);
        float4 h0 = h2f4(r0), h1v = h2f4(r1);
        den += p0 + p1;
#pragma unroll
        for (int h = 0; h < 8; h++) {
            float q0 = __shfl_sync(FULLMASK, p0, h);
            float q1 = __shfl_sync(FULLMASK, p1, h);
            acc[h].x += q0 * h0.x + q1 * h1v.x;
            acc[h].y += q0 * h0.y + q1 * h1v.y;
            acc[h].z += q0 * h0.z + q1 * h1v.z;
            acc[h].w += q0 * h0.w + q1 * h1v.w;
        }
    }
    if (j < deg) {
        int s0 = cp[j];
        float p0 = __expf(lrelu(g_al2[s0 * 8 + hsel] + ar_o) - m);
        float4 h0 = h2f4(hp[(size_t)s0 * 32 + lane]);
        den += p0;
#pragma unroll
        for (int h = 0; h < 8; h++) {
            float q0 = __shfl_sync(FULLMASK, p0, h);
            acc[h].x += q0 * h0.x;
            acc[h].y += q0 * h0.y;
            acc[h].z += q0 * h0.z;
            acc[h].w += q0 * h0.w;
        }
    }
    uint2* ap = (uint2*)(g_aggh + (size_t)n * 1024);
#pragma unroll
    for (int h = 0; h < 8; h++) {
        float dh = __shfl_sync(FULLMASK, den, h);
        float iv = (deg > 0) ? 1.0f / dh : 0.0f;
        ap[h * 32 + lane] = f4h2(make_float4(acc[h].x * iv, acc[h].y * iv, acc[h].z * iv, acc[h].w * iv));
    }
}

// ---------------- GEMM3: out = aggh[N,1024] @ Wbig[1024,40] + b2 (2xTF32 MMA) ----------------
__global__ __launch_bounds__(128) void k_gemm3_tc(const float* __restrict__ b2,
                                                  float* __restrict__ out) {
    __shared__ float As[64][36];
    __shared__ float Bh[32][40];
    __shared__ float Bl[32][40];
    int t = threadIdx.x;
    int lane = t & 31, w = t >> 5;
    int g = lane >> 2, tg = lane & 3;
    int n0 = blockIdx.x * 64;

    float acc[5][4];
#pragma unroll
    for (int nt = 0; nt < 5; nt++)
#pragma unroll
        for (int i = 0; i < 4; i++) acc[nt][i] = 0.f;

    for (int k0 = 0; k0 < 1024; k0 += 32) {
#pragma unroll
        for (int i = 0; i < 4; i++) {
            int f = t + i * 128;
            int r = f >> 3, c4 = f & 7;
            int nn = n0 + r;
            if (nn >= NN) nn = NN - 1;
            uint2 v = *(const uint2*)&g_aggh[(size_t)nn * 1024 + k0 + c4 * 4];
            *(float4*)&As[r][c4 * 4] = h2f4(v);
        }
#pragma unroll
        for (int i = 0; i < 10; i++) {
            int f = t + i * 128;
            int k = f / 40, c = f % 40;
            Bh[k][c] = g_Wb_hi[(size_t)(k0 + k) * 40 + c];
            Bl[k][c] = g_Wb_lo[(size_t)(k0 + k) * 40 + c];
        }
        __syncthreads();
#pragma unroll
        for (int k8 = 0; k8 < 4; k8++) {
            unsigned ah[4];
            ah[0] = f2tf(As[w * 16 + g][k8 * 8 + tg]);
            ah[1] = f2tf(As[w * 16 + g + 8][k8 * 8 + tg]);
            ah[2] = f2tf(As[w * 16 + g][k8 * 8 + tg + 4]);
            ah[3] = f2tf(As[w * 16 + g + 8][k8 * 8 + tg + 4]);
#pragma unroll
            for (int nt = 0; nt < 5; nt++) {
                unsigned bh0 = __float_as_uint(Bh[k8 * 8 + tg][nt * 8 + g]);
                unsigned bh1 = __float_as_uint(Bh[k8 * 8 + tg + 4][nt * 8 + g]);
                unsigned bl0 = __float_as_uint(Bl[k8 * 8 + tg][nt * 8 + g]);
                unsigned bl1 = __float_as_uint(Bl[k8 * 8 + tg + 4][nt * 8 + g]);
                mma_tf32(acc[nt], ah, bh0, bh1);
                mma_tf32(acc[nt], ah, bl0, bl1);
            }
        }
        __syncthreads();
    }

#pragma unroll
    for (int nt = 0; nt < 5; nt++) {
        int col = nt * 8 + 2 * tg;
        float bx = b2[col], by = b2[col + 1];
        int r0 = n0 + w * 16 + g;
        if (r0 < NN) {
            *(float2*)&out[(size_t)r0 * 40 + col] = make_float2(acc[nt][0] + bx, acc[nt][1] + by);
        }
        int r1 = r0 + 8;
        if (r1 < NN) {
            *(float2*)&out[(size_t)r1 * 40 + col] = make_float2(acc[nt][2] + bx, acc[nt][3] + by);
        }
    }
}

// ---------------- host launcher ----------------
// MEASUREMENT ROUND: k_edge1 / k_alpha2 / k_edge2 are idempotent; each is
// launched TWICE. (dur - 891us) = cost of edge1 + alpha2 + edge2 on silicon.
extern "C" void kernel_launch(void* const* d_in, const int* in_sizes, int n_in,
                              void* d_out, int out_size) {
    const float* x = (const float*)d_in[0];
    const void* ei = d_in[1];
    const float* W1 = (const float*)d_in[2];
    const float* as1 = (const float*)d_in[3];
    const float* ad1 = (const float*)d_in[4];
    const float* b1 = (const float*)d_in[5];
    const float* W2 = (const float*)d_in[6];
    const float* as2 = (const float*)d_in[7];
    const float* ad2 = (const float*)d_in[8];
    const float* b2 = (const float*)d_in[9];
    float* out = (float*)d_out;

    k_init<<<98, 1024>>>((const long long*)ei);
    k_hist<<<(NE / 4 + 255) / 256, 256>>>(ei);
    k_scan1<<<25, 1024>>>();
    k_scan2<<<1, 32>>>(25);
    k_scan3<<<25, 1024>>>();
    k_fill<<<(NE / 4 + 255) / 256, 256>>>(ei);
    k_prep_w1<<<64, 256>>>(W1);
    k_gemm1_tc<<<(NN + 63) / 64, 128>>>(x, as1, ad1);
    k_edge1<<<(NN * 32 + 255) / 256, 256>>>(b1);
    k_edge1<<<(NN * 32 + 255) / 256, 256>>>(b1);   // duplicate (measurement)
    k_prep_eff<<<4, 256>>>(W2, as2, ad2);
    k_prep_wbig<<<160, 256>>>(W2);
    k_alpha2<<<592, 256>>>();
    k_alpha2<<<592, 256>>>();                      // duplicate (measurement)
    k_edge2<<<(NN * 32 + 255) / 256, 256>>>();
    k_edge2<<<(NN * 32 + 255) / 256, 256>>>();     // duplicate (measurement)
    k_gemm3_tc<<<(NN + 63) / 64, 128>>>(b2, out);
}

// round 14
// speedup vs baseline: 1.4804x; 1.4804x over previous
#include <cuda_runtime.h>
#include <cuda_fp16.h>

#define NN 100000
#define NE 3200000
#define FULLMASK 0xffffffffu

// ---------------- device scratch ----------------
__device__ int g_cnt[NN];
__device__ int g_rs[NN + 1];
__device__ int g_cur[NN];
__device__ int g_csr[NE];
__device__ int g_bsum[32];
__device__ int g_flag[1];
__device__ unsigned g_almax1[8];
__device__ unsigned g_almax2[8];
__device__ __align__(16) __half g_h1h[(size_t)NN * 128];
__device__ __align__(16) __half g_hAh[(size_t)NN * 128];
__device__ __align__(16) float g_hA[(size_t)NN * 128];
__device__ __align__(16) float g_al1[NN * 8];
__device__ __align__(16) float g_ar1[NN * 8];
__device__ __align__(16) float g_al2[NN * 8];
__device__ __align__(16) float g_ar2[NN * 8];
__device__ __align__(16) float g_wsrc[128 * 8];
__device__ __align__(16) float g_wdst[128 * 8];
__device__ __align__(16) float g_W1h[128 * 128];
__device__ __align__(16) float g_W1l[128 * 128];
__device__ __align__(16) float g_Wb_hi[1024 * 40];
__device__ __align__(16) float g_Wb_lo[1024 * 40];
__device__ __align__(16) __half g_aggh[(size_t)NN * 1024];

// ---------------- helpers ----------------
__device__ __forceinline__ unsigned fkey(float f) {
    unsigned u = __float_as_uint(f);
    return (u & 0x80000000u) ? ~u : (u | 0x80000000u);
}
__device__ __forceinline__ float funkey2(unsigned k) {
    unsigned u = (k & 0x80000000u) ? (k ^ 0x80000000u) : ~k;
    return __uint_as_float(u);
}
__device__ __forceinline__ float lrelu(float e) { return fmaxf(e, 0.2f * e); }

__device__ __forceinline__ unsigned f2tf(float x) {
    unsigned r;
    asm("cvt.rna.tf32.f32 %0, %1;" : "=r"(r) : "f"(x));
    return r;
}

__device__ __forceinline__ void mma_tf32(float* d, const unsigned* a, unsigned b0, unsigned b1) {
    asm volatile(
        "mma.sync.aligned.m16n8k8.row.col.f32.tf32.tf32.f32 "
        "{%0,%1,%2,%3}, {%4,%5,%6,%7}, {%8,%9}, {%0,%1,%2,%3};\n"
        : "+f"(d[0]), "+f"(d[1]), "+f"(d[2]), "+f"(d[3])
        : "r"(a[0]), "r"(a[1]), "r"(a[2]), "r"(a[3]), "r"(b0), "r"(b1));
}

__device__ __forceinline__ void mma_f16(float* c, unsigned a0, unsigned a1, unsigned a2,
                                        unsigned a3, unsigned b0, unsigned b1) {
    asm volatile(
        "mma.sync.aligned.m16n8k16.row.col.f32.f16.f16.f32 "
        "{%0,%1,%2,%3}, {%4,%5,%6,%7}, {%8,%9}, {%0,%1,%2,%3};\n"
        : "+f"(c[0]), "+f"(c[1]), "+f"(c[2]), "+f"(c[3])
        : "r"(a0), "r"(a1), "r"(a2), "r"(a3), "r"(b0), "r"(b1));
}

__device__ __forceinline__ void ldsm4t(unsigned& r0, unsigned& r1, unsigned& r2, unsigned& r3,
                                       unsigned addr) {
    asm volatile("ldmatrix.sync.aligned.m8n8.x4.trans.shared.b16 {%0,%1,%2,%3}, [%4];"
                 : "=r"(r0), "=r"(r1), "=r"(r2), "=r"(r3)
                 : "r"(addr));
}

__device__ __forceinline__ float4 h2f4(uint2 v) {
    __half2 a = *(__half2*)&v.x;
    __half2 b = *(__half2*)&v.y;
    float2 fa = __half22float2(a);
    float2 fb = __half22float2(b);
    return make_float4(fa.x, fa.y, fb.x, fb.y);
}
__device__ __forceinline__ uint2 f4h2(float4 o) {
    uint2 v;
    *(__half2*)&v.x = __float22half2_rn(make_float2(o.x, o.y));
    *(__half2*)&v.y = __float22half2_rn(make_float2(o.z, o.w));
    return v;
}

// ---------------- init ----------------
__global__ void k_init(const long long* ei) {
    int t = threadIdx.x;
    int gid = blockIdx.x * blockDim.x + t;
    for (int i = gid; i < NN; i += gridDim.x * blockDim.x) g_cnt[i] = 0;
    if (blockIdx.x == 0) {
        __shared__ int sbad;
        if (t == 0) sbad = 0;
        __syncthreads();
        int bad = 0;
        for (int i = t; i < 4096; i += blockDim.x) {
            long long v = ei[i];
            if (v < 0 || v >= NN) bad = 1;
        }
        if (bad) atomicOr(&sbad, 1);
        __syncthreads();
        if (t == 0) g_flag[0] = sbad;
        if (t < 8) {
            g_almax1[t] = 0u;
            g_almax2[t] = 0u;
        }
    }
}

// ---------------- histogram of in-degrees (4 edges / thread) ----------------
__global__ void k_hist(const void* ei) {
    int base = (blockIdx.x * blockDim.x + threadIdx.x) * 4;
    if (base >= NE) return;
    int i32 = g_flag[0];
    int d0, d1, d2, d3;
    if (i32) {
        int4 dv = *(const int4*)((const int*)ei + NE + base);
        d0 = dv.x; d1 = dv.y; d2 = dv.z; d3 = dv.w;
    } else {
        const longlong2* p = (const longlong2*)((const long long*)ei + NE + base);
        longlong2 a = p[0], b = p[1];
        d0 = (int)a.x; d1 = (int)a.y; d2 = (int)b.x; d3 = (int)b.y;
    }
    atomicAdd(&g_cnt[d0], 1);
    atomicAdd(&g_cnt[d1], 1);
    atomicAdd(&g_cnt[d2], 1);
    atomicAdd(&g_cnt[d3], 1);
}

// ---------------- coalesced 3-kernel exclusive scan (chunk = 4096) ----------------
__global__ void k_scan1() {
    __shared__ int sw[32];
    int b = blockIdx.x, t = threadIdx.x;
    int base = b * 4096 + t * 4;
    int s = 0;
#pragma unroll
    for (int j = 0; j < 4; j++) {
        int idx = base + j;
        s += (idx < NN) ? g_cnt[idx] : 0;
    }
#pragma unroll
    for (int o = 16; o; o >>= 1) s += __shfl_xor_sync(FULLMASK, s, o);
    if ((t & 31) == 0) sw[t >> 5] = s;
    __syncthreads();
    if (t < 32) {
        int v = sw[t];
#pragma unroll
        for (int o = 16; o; o >>= 1) v += __shfl_xor_sync(FULLMASK, v, o);
        if (t == 0) g_bsum[b] = v;
    }
}

__global__ void k_scan2(int nb) {
    int t = threadIdx.x;
    int v = (t < nb) ? g_bsum[t] : 0;
    int orig = v;
#pragma unroll
    for (int o = 1; o < 32; o <<= 1) {
        int y = __shfl_up_sync(FULLMASK, v, o);
        if (t >= o) v += y;
    }
    if (t < nb) g_bsum[t] = v - orig;
}

__global__ void k_scan3() {
    __shared__ int sw[32];
    int b = blockIdx.x, t = threadIdx.x;
    int lane = t & 31, w = t >> 5;
    int base = b * 4096 + t * 4;
    int v[4];
#pragma unroll
    for (int j = 0; j < 4; j++) {
        int idx = base + j;
        v[j] = (idx < NN) ? g_cnt[idx] : 0;
    }
    int tl = v[0] + v[1] + v[2] + v[3];
    int x = tl;
#pragma unroll
    for (int o = 1; o < 32; o <<= 1) {
        int y = __shfl_up_sync(FULLMASK, x, o);
        if (lane >= o) x += y;
    }
    if (lane == 31) sw[w] = x;
    __syncthreads();
    if (w == 0) {
        int z = sw[lane];
#pragma unroll
        for (int o = 1; o < 32; o <<= 1) {
            int y = __shfl_up_sync(FULLMASK, z, o);
            if (lane >= o) z += y;
        }
        sw[lane] = z;
    }
    __syncthreads();
    int woff = (w > 0) ? sw[w - 1] : 0;
    int run = g_bsum[b] + woff + (x - tl);
#pragma unroll
    for (int j = 0; j < 4; j++) {
        int idx = base + j;
        if (idx <= NN) {
            g_rs[idx] = run;
            if (idx < NN) g_cur[idx] = run;
        }
        run += v[j];
    }
}

// ---------------- CSR fill (4 edges / thread) ----------------
__global__ void k_fill(const void* ei) {
    int base = (blockIdx.x * blockDim.x + threadIdx.x) * 4;
    if (base >= NE) return;
    int i32 = g_flag[0];
    int s0, s1, s2, s3, d0, d1, d2, d3;
    if (i32) {
        int4 sv = *(const int4*)((const int*)ei + base);
        int4 dv = *(const int4*)((const int*)ei + NE + base);
        s0 = sv.x; s1 = sv.y; s2 = sv.z; s3 = sv.w;
        d0 = dv.x; d1 = dv.y; d2 = dv.z; d3 = dv.w;
    } else {
        const longlong2* ps = (const longlong2*)((const long long*)ei + base);
        const longlong2* pd = (const longlong2*)((const long long*)ei + NE + base);
        longlong2 a = ps[0], b = ps[1];
        longlong2 c = pd[0], e = pd[1];
        s0 = (int)a.x; s1 = (int)a.y; s2 = (int)b.x; s3 = (int)b.y;
        d0 = (int)c.x; d1 = (int)c.y; d2 = (int)e.x; d3 = (int)e.y;
    }
    int p0 = atomicAdd(&g_cur[d0], 1);
    int p1 = atomicAdd(&g_cur[d1], 1);
    int p2 = atomicAdd(&g_cur[d2], 1);
    int p3 = atomicAdd(&g_cur[d3], 1);
    g_csr[p0] = s0;
    g_csr[p1] = s1;
    g_csr[p2] = s2;
    g_csr[p3] = s3;
}

// ---------------- weight prep ----------------
__global__ void k_prep_eff(const float* __restrict__ W2, const float* __restrict__ as2,
                           const float* __restrict__ ad2) {
    int t = blockIdx.x * blockDim.x + threadIdx.x;
    if (t >= 1024) return;
    int k = t >> 3, h = t & 7;
    float s = 0.f, d = 0.f;
    for (int c = 0; c < 40; c++) {
        float w = W2[k * 320 + h * 40 + c];
        s += w * as2[h * 40 + c];
        d += w * ad2[h * 40 + c];
    }
    g_wsrc[t] = s;
    g_wdst[t] = d;
}

__global__ void k_prep_wbig(const float* __restrict__ W2) {
    int t = blockIdx.x * blockDim.x + threadIdx.x;
    if (t >= 40960) return;
    int i = t / 40, c = t % 40;
    int h = i >> 7, k = i & 127;
    float wv = W2[k * 320 + h * 40 + c] * 0.125f;
    float hif = __uint_as_float(f2tf(wv));
    g_Wb_hi[t] = hif;
    g_Wb_lo[t] = __uint_as_float(f2tf(wv - hif));
}

__global__ void k_prep_w1(const float* __restrict__ W1) {
    int t = blockIdx.x * blockDim.x + threadIdx.x;
    if (t >= 16384) return;
    float v = W1[t];
    float hif = __uint_as_float(f2tf(v));
    g_W1h[t] = hif;
    g_W1l[t] = __uint_as_float(f2tf(v - hif));
}

// ---------------- GEMM1 (3xTF32 MMA): h1h = x @ W1, fused alpha1 ----------------
__global__ __launch_bounds__(128) void k_gemm1_tc(const float* __restrict__ x,
                                                  const float* __restrict__ as1,
                                                  const float* __restrict__ ad1) {
    __shared__ float As[64][36];
    __shared__ union {
        struct {
            float Wh[32][132];
            float Wl[32][132];
        } w;
        __half Hs[64][144];
    } U;
    __shared__ unsigned salmax[8];
    int t = threadIdx.x;
    int lane = t & 31, w = t >> 5;
    int g = lane >> 2, tg = lane & 3;
    int n0 = blockIdx.x * 64;
    if (t < 8) salmax[t] = 0u;

    float acc[16][4];
#pragma unroll
    for (int nt = 0; nt < 16; nt++)
#pragma unroll
        for (int i = 0; i < 4; i++) acc[nt][i] = 0.f;

    for (int k0 = 0; k0 < 128; k0 += 32) {
#pragma unroll
        for (int i = 0; i < 4; i++) {
            int f = t + i * 128;
            int r = f >> 3, c4 = f & 7;
            int nn = n0 + r;
            if (nn >= NN) nn = NN - 1;
            float4 v = *(const float4*)&x[(size_t)nn * 128 + k0 + c4 * 4];
            *(float4*)&As[r][c4 * 4] = v;
        }
#pragma unroll
        for (int i = 0; i < 8; i++) {
            int f = t + i * 128;
            int kr = f >> 5, c4 = f & 31;
            *(float4*)&U.w.Wh[kr][c4 * 4] = *(const float4*)&g_W1h[(size_t)(k0 + kr) * 128 + c4 * 4];
            *(float4*)&U.w.Wl[kr][c4 * 4] = *(const float4*)&g_W1l[(size_t)(k0 + kr) * 128 + c4 * 4];
        }
        __syncthreads();
#pragma unroll
        for (int k8 = 0; k8 < 4; k8++) {
            float a0 = As[w * 16 + g][k8 * 8 + tg];
            float a1 = As[w * 16 + g + 8][k8 * 8 + tg];
            float a2 = As[w * 16 + g][k8 * 8 + tg + 4];
            float a3 = As[w * 16 + g + 8][k8 * 8 + tg + 4];
            unsigned ah[4], al[4];
            ah[0] = f2tf(a0);
            ah[1] = f2tf(a1);
            ah[2] = f2tf(a2);
            ah[3] = f2tf(a3);
            al[0] = f2tf(a0 - __uint_as_float(ah[0]));
            al[1] = f2tf(a1 - __uint_as_float(ah[1]));
            al[2] = f2tf(a2 - __uint_as_float(ah[2]));
            al[3] = f2tf(a3 - __uint_as_float(ah[3]));
#pragma unroll
            for (int nt = 0; nt < 16; nt++) {
                unsigned bh0 = __float_as_uint(U.w.Wh[k8 * 8 + tg][nt * 8 + g]);
                unsigned bh1 = __float_as_uint(U.w.Wh[k8 * 8 + tg + 4][nt * 8 + g]);
                unsigned bl0 = __float_as_uint(U.w.Wl[k8 * 8 + tg][nt * 8 + g]);
                unsigned bl1 = __float_as_uint(U.w.Wl[k8 * 8 + tg + 4][nt * 8 + g]);
                mma_tf32(acc[nt], ah, bh0, bh1);
                mma_tf32(acc[nt], ah, bl0, bl1);
                mma_tf32(acc[nt], al, bh0, bh1);
            }
        }
        __syncthreads();
    }

#pragma unroll
    for (int nt = 0; nt < 16; nt++) {
        int col = nt * 8 + 2 * tg;
        *(__half2*)&U.Hs[w * 16 + g][col] = __float22half2_rn(make_float2(acc[nt][0], acc[nt][1]));
        *(__half2*)&U.Hs[w * 16 + g + 8][col] = __float22half2_rn(make_float2(acc[nt][2], acc[nt][3]));
    }

    int r0 = n0 + w * 16 + g;
    int r1 = r0 + 8;
#pragma unroll
    for (int h = 0; h < 8; h++) {
        float s0 = 0.f, d0 = 0.f, s1 = 0.f, d1 = 0.f;
#pragma unroll
        for (int q = 0; q < 2; q++) {
            int nt = 2 * h + q;
            int col = nt * 8 + 2 * tg;
            float wa0 = as1[col], wa1 = as1[col + 1];
            float wd0 = ad1[col], wd1 = ad1[col + 1];
            s0 += acc[nt][0] * wa0 + acc[nt][1] * wa1;
            d0 += acc[nt][0] * wd0 + acc[nt][1] * wd1;
            s1 += acc[nt][2] * wa0 + acc[nt][3] * wa1;
            d1 += acc[nt][2] * wd0 + acc[nt][3] * wd1;
        }
        s0 += __shfl_xor_sync(FULLMASK, s0, 1);
        s0 += __shfl_xor_sync(FULLMASK, s0, 2);
        d0 += __shfl_xor_sync(FULLMASK, d0, 1);
        d0 += __shfl_xor_sync(FULLMASK, d0, 2);
        s1 += __shfl_xor_sync(FULLMASK, s1, 1);
        s1 += __shfl_xor_sync(FULLMASK, s1, 2);
        d1 += __shfl_xor_sync(FULLMASK, d1, 1);
        d1 += __shfl_xor_sync(FULLMASK, d1, 2);
        if (tg == 0) {
            if (r0 < NN) {
                g_al1[r0 * 8 + h] = s0;
                g_ar1[r0 * 8 + h] = d0;
                atomicMax(&salmax[h], fkey(s0));
            }
            if (r1 < NN) {
                g_al1[r1 * 8 + h] = s1;
                g_ar1[r1 * 8 + h] = d1;
                atomicMax(&salmax[h], fkey(s1));
            }
        }
    }
    __syncthreads();

    {
        int r = t >> 1;
        int row = n0 + r;
        int ch = (t & 1) * 64;
        if (row < NN) {
            uint4 buf[8];
#pragma unroll
            for (int i = 0; i < 8; i++) buf[i] = *(uint4*)&U.Hs[r][ch + i * 8];
#pragma unroll
            for (int i = 0; i < 8; i++) *(uint4*)&g_h1h[(size_t)row * 128 + ch + i * 8] = buf[i];
        }
    }
    if (t < 8) atomicMax(&g_almax1[t], salmax[t]);
}

// ---------------- edge1: warp/dst, unroll-4, half gather rows ----------------
__global__ __launch_bounds__(256) void k_edge1(const float* __restrict__ b1) {
    int gw = (blockIdx.x * blockDim.x + threadIdx.x) >> 5;
    int lane = threadIdx.x & 31;
    if (gw >= NN) return;
    int n = gw;
    int beg = g_rs[n], deg = g_rs[n + 1] - beg;
    int head = lane >> 2;
    float ar_h = g_ar1[n * 8 + head];
    float m = lrelu(funkey2(g_almax1[head]) + ar_h);

    float4 acc = make_float4(0.f, 0.f, 0.f, 0.f);
    float den = 0.f;
    const uint2* hp = (const uint2*)g_h1h;
    const int* cp = g_csr + beg;
    int j = 0;
    for (; j + 3 < deg; j += 4) {
        int s0 = cp[j], s1 = cp[j + 1], s2 = cp[j + 2], s3 = cp[j + 3];
        float a0 = g_al1[s0 * 8 + head];
        float a1 = g_al1[s1 * 8 + head];
        float a2 = g_al1[s2 * 8 + head];
        float a3 = g_al1[s3 * 8 + head];
        uint2 r0 = hp[(size_t)s0 * 32 + lane];
        uint2 r1 = hp[(size_t)s1 * 32 + lane];
        uint2 r2 = hp[(size_t)s2 * 32 + lane];
        uint2 r3 = hp[(size_t)s3 * 32 + lane];
        float p0 = __expf(lrelu(a0 + ar_h) - m);
        float p1 = __expf(lrelu(a1 + ar_h) - m);
        float p2 = __expf(lrelu(a2 + ar_h) - m);
        float p3 = __expf(lrelu(a3 + ar_h) - m);
        float4 h0 = h2f4(r0), h1v = h2f4(r1), h2v = h2f4(r2), h3v = h2f4(r3);
        den += (p0 + p1) + (p2 + p3);
        acc.x += p0 * h0.x + p1 * h1v.x + p2 * h2v.x + p3 * h3v.x;
        acc.y += p0 * h0.y + p1 * h1v.y + p2 * h2v.y + p3 * h3v.y;
        acc.z += p0 * h0.z + p1 * h1v.z + p2 * h2v.z + p3 * h3v.z;
        acc.w += p0 * h0.w + p1 * h1v.w + p2 * h2v.w + p3 * h3v.w;
    }
    for (; j < deg; j++) {
        int s0 = cp[j];
        float p0 = __expf(lrelu(g_al1[s0 * 8 + head] + ar_h) - m);
        float4 h0 = h2f4(hp[(size_t)s0 * 32 + lane]);
        den += p0;
        acc.x += p0 * h0.x;
        acc.y += p0 * h0.y;
        acc.z += p0 * h0.z;
        acc.w += p0 * h0.w;
    }
    float inv = (deg > 0) ? 1.0f / den : 0.0f;
    float4 bb = ((const float4*)b1)[lane];
    float4 o;
    o.x = acc.x * inv + bb.x;
    o.y = acc.y * inv + bb.y;
    o.z = acc.z * inv + bb.z;
    o.w = acc.w * inv + bb.w;
    o.x = o.x > 0.f ? o.x : (__expf(o.x) - 1.f);
    o.y = o.y > 0.f ? o.y : (__expf(o.y) - 1.f);
    o.z = o.z > 0.f ? o.z : (__expf(o.z) - 1.f);
    o.w = o.w > 0.f ? o.w : (__expf(o.w) - 1.f);
    ((float4*)g_hA)[(size_t)n * 32 + lane] = o;
    ((uint2*)g_hAh)[(size_t)n * 32 + lane] = f4h2(o);
}

// ---------------- alpha2 + almax2 tracking (separate, streaming, fp32) ----------------
__global__ __launch_bounds__(256) void k_alpha2() {
    __shared__ unsigned smax[8];
    int t = threadIdx.x;
    if (t < 8) smax[t] = 0u;
    __syncthreads();
    int wid = (blockIdx.x * blockDim.x + t) >> 5;
    int lane = t & 31;
    int nwarp = (gridDim.x * blockDim.x) >> 5;
    float ws[4][8], wd[4][8];
#pragma unroll
    for (int j = 0; j < 4; j++) {
        int k = lane * 4 + j;
#pragma unroll
        for (int h = 0; h < 8; h++) {
            ws[j][h] = g_wsrc[k * 8 + h];
            wd[j][h] = g_wdst[k * 8 + h];
        }
    }
    float lmax[8];
#pragma unroll
    for (int h = 0; h < 8; h++) lmax[h] = -1e30f;
    for (int n = wid; n < NN; n += nwarp) {
        float4 hv = ((const float4*)g_hA)[(size_t)n * 32 + lane];
        float hvv[4] = {hv.x, hv.y, hv.z, hv.w};
        float as[8], ad[8];
#pragma unroll
        for (int h = 0; h < 8; h++) {
            as[h] = 0.f;
            ad[h] = 0.f;
        }
#pragma unroll
        for (int j = 0; j < 4; j++)
#pragma unroll
            for (int h = 0; h < 8; h++) {
                as[h] += hvv[j] * ws[j][h];
                ad[h] += hvv[j] * wd[j][h];
            }
#pragma unroll
        for (int h = 0; h < 8; h++) {
#pragma unroll
            for (int o = 16; o; o >>= 1) {
                as[h] += __shfl_xor_sync(FULLMASK, as[h], o);
                ad[h] += __shfl_xor_sync(FULLMASK, ad[h], o);
            }
        }
        if (lane == 0) {
#pragma unroll
            for (int h = 0; h < 8; h++) {
                g_al2[n * 8 + h] = as[h];
                g_ar2[n * 8 + h] = ad[h];
                lmax[h] = fmaxf(lmax[h], as[h]);
            }
        }
    }
    if (lane == 0) {
#pragma unroll
        for (int h = 0; h < 8; h++) atomicMax(&smax[h], fkey(lmax[h]));
    }
    __syncthreads();
    if (t < 8) atomicMax(&g_almax2[t], smax[t]);
}

// ---------------- edge2 TENSOR: warp/node, fp16 m16n8k16 MMA ----------------
// aggT[128 feat, 8 heads] = H[feat, edges] @ P[edges, heads] per 16-edge chunk.
__global__ __launch_bounds__(256) void k_edge2_tc() {
    __shared__ __half tile[8][16][136];
    int t = threadIdx.x;
    int wid = t >> 5, lane = t & 31;
    int g = lane >> 2, tg = lane & 3;
    int n = blockIdx.x * 8 + wid;
    if (n >= NN) return;
    int beg = g_rs[n], deg = g_rs[n + 1] - beg;
    __half* wtile = &tile[wid][0][0];

    if (deg == 0) {
        uint2* outp = (uint2*)(g_aggh + (size_t)n * 1024);
        uint2 z = make_uint2(0u, 0u);
        for (int i = lane; i < 256; i += 32) outp[i] = z;
        return;
    }

    float ar_g = g_ar2[n * 8 + g];
    float m_g = lrelu(funkey2(g_almax2[g]) + ar_g);
    const int* cp = g_csr + beg;

    float c[8][4];
#pragma unroll
    for (int f = 0; f < 8; f++) {
        c[f][0] = 0.f; c[f][1] = 0.f; c[f][2] = 0.f; c[f][3] = 0.f;
    }
    float den = 0.f;

    int arow = (lane & 7) | ((lane >> 1) & 8);
    int acol = lane & 8;
    unsigned abase = (unsigned)__cvta_generic_to_shared(&tile[wid][arow][acol]);

    for (int j0 = 0; j0 < deg; j0 += 16) {
        __syncwarp();
        // gather 16 rows (256B each): lane -> row lane>>1, half (lane&1)
        {
            int r = lane >> 1;
            int hh = lane & 1;
            int ej = j0 + r;
            if (ej >= deg) ej = deg - 1;
            int src = cp[ej];
            const uint4* rp = (const uint4*)(g_hAh + (size_t)src * 128 + hh * 64);
            uint4* dp = (uint4*)&tile[wid][r][hh * 64];
#pragma unroll
            for (int i = 0; i < 8; i++) dp[i] = rp[i];
        }
        // B fragment in registers: head g, edges tg*2, tg*2+1, tg*2+8, tg*2+9
        float pv[4];
#pragma unroll
        for (int q = 0; q < 4; q++) {
            int eo = (q & 1) + ((q >> 1) << 3) + tg * 2;  // 0,1,8,9 offsets
            int e = j0 + eo;
            float p = 0.f;
            if (e < deg) {
                int s = cp[e];
                p = __expf(lrelu(g_al2[s * 8 + g] + ar_g) - m_g);
            }
            pv[q] = p;
        }
        __half2 b0h = __floats2half2_rn(pv[0], pv[1]);
        __half2 b1h = __floats2half2_rn(pv[2], pv[3]);
        // den from fp16-rounded p so numerator/denominator rounding cancels
        float2 f0 = __half22float2(b0h), f1 = __half22float2(b1h);
        den += (f0.x + f0.y) + (f1.x + f1.y);
        unsigned b0 = *(unsigned*)&b0h, b1 = *(unsigned*)&b1h;
        __syncwarp();
#pragma unroll
        for (int f = 0; f < 8; f++) {
            unsigned a0, a1, a2, a3;
            ldsm4t(a0, a1, a2, a3, abase + f * 32);
            mma_f16(c[f], a0, a1, a2, a3, b0, b1);
        }
    }

    den += __shfl_xor_sync(FULLMASK, den, 1);
    den += __shfl_xor_sync(FULLMASK, den, 2);
    float d0 = __shfl_sync(FULLMASK, den, (2 * tg) * 4);
    float d1 = __shfl_sync(FULLMASK, den, (2 * tg + 1) * 4);
    float iv0 = (d0 > 0.f) ? 1.f / d0 : 0.f;
    float iv1 = (d1 > 0.f) ? 1.f / d1 : 0.f;

    __syncwarp();
    // stage C to smem as [head][136 halves]
#pragma unroll
    for (int f = 0; f < 8; f++) {
        wtile[(2 * tg) * 136 + f * 16 + g] = __float2half_rn(c[f][0] * iv0);
        wtile[(2 * tg + 1) * 136 + f * 16 + g] = __float2half_rn(c[f][1] * iv1);
        wtile[(2 * tg) * 136 + f * 16 + g + 8] = __float2half_rn(c[f][2] * iv0);
        wtile[(2 * tg + 1) * 136 + f * 16 + g + 8] = __float2half_rn(c[f][3] * iv1);
    }
    __syncwarp();
    uint2* outp = (uint2*)(g_aggh + (size_t)n * 1024);
#pragma unroll
    for (int h = 0; h < 8; h++) {
        uint2 v = *(uint2*)&wtile[h * 136 + lane * 4];
        outp[h * 32 + lane] = v;
    }
}

// ---------------- GEMM3: out = aggh[N,1024] @ Wbig[1024,40] + b2 (2xTF32 MMA) ----------------
__global__ __launch_bounds__(128) void k_gemm3_tc(const float* __restrict__ b2,
                                                  float* __restrict__ out) {
    __shared__ float As[64][36];
    __shared__ float Bh[32][40];
    __shared__ float Bl[32][40];
    int t = threadIdx.x;
    int lane = t & 31, w = t >> 5;
    int g = lane >> 2, tg = lane & 3;
    int n0 = blockIdx.x * 64;

    float acc[5][4];
#pragma unroll
    for (int nt = 0; nt < 5; nt++)
#pragma unroll
        for (int i = 0; i < 4; i++) acc[nt][i] = 0.f;

    for (int k0 = 0; k0 < 1024; k0 += 32) {
#pragma unroll
        for (int i = 0; i < 4; i++) {
            int f = t + i * 128;
            int r = f >> 3, c4 = f & 7;
            int nn = n0 + r;
            if (nn >= NN) nn = NN - 1;
            uint2 v = *(const uint2*)&g_aggh[(size_t)nn * 1024 + k0 + c4 * 4];
            *(float4*)&As[r][c4 * 4] = h2f4(v);
        }
#pragma unroll
        for (int i = 0; i < 10; i++) {
            int f = t + i * 128;
            int k = f / 40, c = f % 40;
            Bh[k][c] = g_Wb_hi[(size_t)(k0 + k) * 40 + c];
            Bl[k][c] = g_Wb_lo[(size_t)(k0 + k) * 40 + c];
        }
        __syncthreads();
#pragma unroll
        for (int k8 = 0; k8 < 4; k8++) {
            unsigned ah[4];
            ah[0] = f2tf(As[w * 16 + g][k8 * 8 + tg]);
            ah[1] = f2tf(As[w * 16 + g + 8][k8 * 8 + tg]);
            ah[2] = f2tf(As[w * 16 + g][k8 * 8 + tg + 4]);
            ah[3] = f2tf(As[w * 16 + g + 8][k8 * 8 + tg + 4]);
#pragma unroll
            for (int nt = 0; nt < 5; nt++) {
                unsigned bh0 = __float_as_uint(Bh[k8 * 8 + tg][nt * 8 + g]);
                unsigned bh1 = __float_as_uint(Bh[k8 * 8 + tg + 4][nt * 8 + g]);
                unsigned bl0 = __float_as_uint(Bl[k8 * 8 + tg][nt * 8 + g]);
                unsigned bl1 = __float_as_uint(Bl[k8 * 8 + tg + 4][nt * 8 + g]);
                mma_tf32(acc[nt], ah, bh0, bh1);
                mma_tf32(acc[nt], ah, bl0, bl1);
            }
        }
        __syncthreads();
    }

#pragma unroll
    for (int nt = 0; nt < 5; nt++) {
        int col = nt * 8 + 2 * tg;
        float bx = b2[col], by = b2[col + 1];
        int r0 = n0 + w * 16 + g;
        if (r0 < NN) {
            *(float2*)&out[(size_t)r0 * 40 + col] = make_float2(acc[nt][0] + bx, acc[nt][1] + by);
        }
        int r1 = r0 + 8;
        if (r1 < NN) {
            *(float2*)&out[(size_t)r1 * 40 + col] = make_float2(acc[nt][2] + bx, acc[nt][3] + by);
        }
    }
}

// ---------------- host launcher ----------------
extern "C" void kernel_launch(void* const* d_in, const int* in_sizes, int n_in,
                              void* d_out, int out_size) {
    const float* x = (const float*)d_in[0];
    const void* ei = d_in[1];
    const float* W1 = (const float*)d_in[2];
    const float* as1 = (const float*)d_in[3];
    const float* ad1 = (const float*)d_in[4];
    const float* b1 = (const float*)d_in[5];
    const float* W2 = (const float*)d_in[6];
    const float* as2 = (const float*)d_in[7];
    const float* ad2 = (const float*)d_in[8];
    const float* b2 = (const float*)d_in[9];
    float* out = (float*)d_out;

    k_init<<<98, 1024>>>((const long long*)ei);
    k_hist<<<(NE / 4 + 255) / 256, 256>>>(ei);
    k_scan1<<<25, 1024>>>();
    k_scan2<<<1, 32>>>(25);
    k_scan3<<<25, 1024>>>();
    k_fill<<<(NE / 4 + 255) / 256, 256>>>(ei);
    k_prep_w1<<<64, 256>>>(W1);
    k_gemm1_tc<<<(NN + 63) / 64, 128>>>(x, as1, ad1);
    k_edge1<<<(NN * 32 + 255) / 256, 256>>>(b1);
    k_prep_eff<<<4, 256>>>(W2, as2, ad2);
    k_prep_wbig<<<160, 256>>>(W2);
    k_alpha2<<<592, 256>>>();
    k_edge2_tc<<<(NN + 7) / 8, 256>>>();
    k_gemm3_tc<<<(NN + 63) / 64, 128>>>(b2, out);
}

// round 16
// speedup vs baseline: 1.6381x; 1.1065x over previous
#include <cuda_runtime.h>
#include <cuda_fp16.h>

#define NN 100000
#define NE 3200000
#define FULLMASK 0xffffffffu

// ---------------- device scratch ----------------
__device__ int g_cnt[NN];
__device__ int g_rs[NN + 1];
__device__ int g_cur[NN];
__device__ int g_csr[NE];
__device__ int g_bsum[32];
__device__ int g_flag[1];
__device__ unsigned g_almax1[8];
__device__ unsigned g_almax2[8];
__device__ __align__(16) __half g_h1h[(size_t)NN * 128];
__device__ __align__(16) __half g_hAh[(size_t)NN * 128];
__device__ __align__(16) float g_hA[(size_t)NN * 128];
__device__ __align__(16) float g_al1[NN * 8];
__device__ __align__(16) float g_ar1[NN * 8];
__device__ __align__(16) float g_al2[NN * 8];
__device__ __align__(16) float g_ar2[NN * 8];
__device__ __align__(16) float g_wsrc[128 * 8];
__device__ __align__(16) float g_wdst[128 * 8];
__device__ __align__(16) float g_W1h[128 * 128];
__device__ __align__(16) float g_W1l[128 * 128];
__device__ __align__(16) float g_Wb_hi[1024 * 40];
__device__ __align__(16) float g_Wb_lo[1024 * 40];
__device__ __align__(16) __half g_aggh[(size_t)NN * 1024];

// ---------------- helpers ----------------
__device__ __forceinline__ unsigned fkey(float f) {
    unsigned u = __float_as_uint(f);
    return (u & 0x80000000u) ? ~u : (u | 0x80000000u);
}
__device__ __forceinline__ float funkey2(unsigned k) {
    unsigned u = (k & 0x80000000u) ? (k ^ 0x80000000u) : ~k;
    return __uint_as_float(u);
}
__device__ __forceinline__ float lrelu(float e) { return fmaxf(e, 0.2f * e); }

__device__ __forceinline__ unsigned f2tf(float x) {
    unsigned r;
    asm("cvt.rna.tf32.f32 %0, %1;" : "=r"(r) : "f"(x));
    return r;
}

__device__ __forceinline__ void mma_tf32(float* d, const unsigned* a, unsigned b0, unsigned b1) {
    asm volatile(
        "mma.sync.aligned.m16n8k8.row.col.f32.tf32.tf32.f32 "
        "{%0,%1,%2,%3}, {%4,%5,%6,%7}, {%8,%9}, {%0,%1,%2,%3};\n"
        : "+f"(d[0]), "+f"(d[1]), "+f"(d[2]), "+f"(d[3])
        : "r"(a[0]), "r"(a[1]), "r"(a[2]), "r"(a[3]), "r"(b0), "r"(b1));
}

__device__ __forceinline__ void mma_f16(float* c, unsigned a0, unsigned a1, unsigned a2,
                                        unsigned a3, unsigned b0, unsigned b1) {
    asm volatile(
        "mma.sync.aligned.m16n8k16.row.col.f32.f16.f16.f32 "
        "{%0,%1,%2,%3}, {%4,%5,%6,%7}, {%8,%9}, {%0,%1,%2,%3};\n"
        : "+f"(c[0]), "+f"(c[1]), "+f"(c[2]), "+f"(c[3])
        : "r"(a0), "r"(a1), "r"(a2), "r"(a3), "r"(b0), "r"(b1));
}

__device__ __forceinline__ void ldsm4t(unsigned& r0, unsigned& r1, unsigned& r2, unsigned& r3,
                                       unsigned addr) {
    asm volatile("ldmatrix.sync.aligned.m8n8.x4.trans.shared.b16 {%0,%1,%2,%3}, [%4];"
                 : "=r"(r0), "=r"(r1), "=r"(r2), "=r"(r3)
                 : "r"(addr));
}

__device__ __forceinline__ float4 h2f4(uint2 v) {
    __half2 a = *(__half2*)&v.x;
    __half2 b = *(__half2*)&v.y;
    float2 fa = __half22float2(a);
    float2 fb = __half22float2(b);
    return make_float4(fa.x, fa.y, fb.x, fb.y);
}
__device__ __forceinline__ uint2 f4h2(float4 o) {
    uint2 v;
    *(__half2*)&v.x = __float22half2_rn(make_float2(o.x, o.y));
    *(__half2*)&v.y = __float22half2_rn(make_float2(o.z, o.w));
    return v;
}

// ---------------- init ----------------
__global__ void k_init(const long long* ei) {
    int t = threadIdx.x;
    int gid = blockIdx.x * blockDim.x + t;
    for (int i = gid; i < NN; i += gridDim.x * blockDim.x) g_cnt[i] = 0;
    if (blockIdx.x == 0) {
        __shared__ int sbad;
        if (t == 0) sbad = 0;
        __syncthreads();
        int bad = 0;
        for (int i = t; i < 4096; i += blockDim.x) {
            long long v = ei[i];
            if (v < 0 || v >= NN) bad = 1;
        }
        if (bad) atomicOr(&sbad, 1);
        __syncthreads();
        if (t == 0) g_flag[0] = sbad;
        if (t < 8) {
            g_almax1[t] = 0u;
            g_almax2[t] = 0u;
        }
    }
}

// ---------------- histogram of in-degrees (4 edges / thread) ----------------
__global__ void k_hist(const void* ei) {
    int base = (blockIdx.x * blockDim.x + threadIdx.x) * 4;
    if (base >= NE) return;
    int i32 = g_flag[0];
    int d0, d1, d2, d3;
    if (i32) {
        int4 dv = *(const int4*)((const int*)ei + NE + base);
        d0 = dv.x; d1 = dv.y; d2 = dv.z; d3 = dv.w;
    } else {
        const longlong2* p = (const longlong2*)((const long long*)ei + NE + base);
        longlong2 a = p[0], b = p[1];
        d0 = (int)a.x; d1 = (int)a.y; d2 = (int)b.x; d3 = (int)b.y;
    }
    atomicAdd(&g_cnt[d0], 1);
    atomicAdd(&g_cnt[d1], 1);
    atomicAdd(&g_cnt[d2], 1);
    atomicAdd(&g_cnt[d3], 1);
}

// ---------------- coalesced 3-kernel exclusive scan (chunk = 4096) ----------------
__global__ void k_scan1() {
    __shared__ int sw[32];
    int b = blockIdx.x, t = threadIdx.x;
    int base = b * 4096 + t * 4;
    int s = 0;
#pragma unroll
    for (int j = 0; j < 4; j++) {
        int idx = base + j;
        s += (idx < NN) ? g_cnt[idx] : 0;
    }
#pragma unroll
    for (int o = 16; o; o >>= 1) s += __shfl_xor_sync(FULLMASK, s, o);
    if ((t & 31) == 0) sw[t >> 5] = s;
    __syncthreads();
    if (t < 32) {
        int v = sw[t];
#pragma unroll
        for (int o = 16; o; o >>= 1) v += __shfl_xor_sync(FULLMASK, v, o);
        if (t == 0) g_bsum[b] = v;
    }
}

__global__ void k_scan2(int nb) {
    int t = threadIdx.x;
    int v = (t < nb) ? g_bsum[t] : 0;
    int orig = v;
#pragma unroll
    for (int o = 1; o < 32; o <<= 1) {
        int y = __shfl_up_sync(FULLMASK, v, o);
        if (t >= o) v += y;
    }
    if (t < nb) g_bsum[t] = v - orig;
}

__global__ void k_scan3() {
    __shared__ int sw[32];
    int b = blockIdx.x, t = threadIdx.x;
    int lane = t & 31, w = t >> 5;
    int base = b * 4096 + t * 4;
    int v[4];
#pragma unroll
    for (int j = 0; j < 4; j++) {
        int idx = base + j;
        v[j] = (idx < NN) ? g_cnt[idx] : 0;
    }
    int tl = v[0] + v[1] + v[2] + v[3];
    int x = tl;
#pragma unroll
    for (int o = 1; o < 32; o <<= 1) {
        int y = __shfl_up_sync(FULLMASK, x, o);
        if (lane >= o) x += y;
    }
    if (lane == 31) sw[w] = x;
    __syncthreads();
    if (w == 0) {
        int z = sw[lane];
#pragma unroll
        for (int o = 1; o < 32; o <<= 1) {
            int y = __shfl_up_sync(FULLMASK, z, o);
            if (lane >= o) z += y;
        }
        sw[lane] = z;
    }
    __syncthreads();
    int woff = (w > 0) ? sw[w - 1] : 0;
    int run = g_bsum[b] + woff + (x - tl);
#pragma unroll
    for (int j = 0; j < 4; j++) {
        int idx = base + j;
        if (idx <= NN) {
            g_rs[idx] = run;
            if (idx < NN) g_cur[idx] = run;
        }
        run += v[j];
    }
}

// ---------------- CSR fill (4 edges / thread) ----------------
__global__ void k_fill(const void* ei) {
    int base = (blockIdx.x * blockDim.x + threadIdx.x) * 4;
    if (base >= NE) return;
    int i32 = g_flag[0];
    int s0, s1, s2, s3, d0, d1, d2, d3;
    if (i32) {
        int4 sv = *(const int4*)((const int*)ei + base);
        int4 dv = *(const int4*)((const int*)ei + NE + base);
        s0 = sv.x; s1 = sv.y; s2 = sv.z; s3 = sv.w;
        d0 = dv.x; d1 = dv.y; d2 = dv.z; d3 = dv.w;
    } else {
        const longlong2* ps = (const longlong2*)((const long long*)ei + base);
        const longlong2* pd = (const longlong2*)((const long long*)ei + NE + base);
        longlong2 a = ps[0], b = ps[1];
        longlong2 c = pd[0], e = pd[1];
        s0 = (int)a.x; s1 = (int)a.y; s2 = (int)b.x; s3 = (int)b.y;
        d0 = (int)c.x; d1 = (int)c.y; d2 = (int)e.x; d3 = (int)e.y;
    }
    int p0 = atomicAdd(&g_cur[d0], 1);
    int p1 = atomicAdd(&g_cur[d1], 1);
    int p2 = atomicAdd(&g_cur[d2], 1);
    int p3 = atomicAdd(&g_cur[d3], 1);
    g_csr[p0] = s0;
    g_csr[p1] = s1;
    g_csr[p2] = s2;
    g_csr[p3] = s3;
}

// ---------------- weight prep ----------------
__global__ void k_prep_eff(const float* __restrict__ W2, const float* __restrict__ as2,
                           const float* __restrict__ ad2) {
    int t = blockIdx.x * blockDim.x + threadIdx.x;
    if (t >= 1024) return;
    int k = t >> 3, h = t & 7;
    float s = 0.f, d = 0.f;
    for (int c = 0; c < 40; c++) {
        float w = W2[k * 320 + h * 40 + c];
        s += w * as2[h * 40 + c];
        d += w * ad2[h * 40 + c];
    }
    g_wsrc[t] = s;
    g_wdst[t] = d;
}

__global__ void k_prep_wbig(const float* __restrict__ W2) {
    int t = blockIdx.x * blockDim.x + threadIdx.x;
    if (t >= 40960) return;
    int i = t / 40, c = t % 40;
    int h = i >> 7, k = i & 127;
    float wv = W2[k * 320 + h * 40 + c] * 0.125f;
    float hif = __uint_as_float(f2tf(wv));
    g_Wb_hi[t] = hif;
    g_Wb_lo[t] = __uint_as_float(f2tf(wv - hif));
}

__global__ void k_prep_w1(const float* __restrict__ W1) {
    int t = blockIdx.x * blockDim.x + threadIdx.x;
    if (t >= 16384) return;
    float v = W1[t];
    float hif = __uint_as_float(f2tf(v));
    g_W1h[t] = hif;
    g_W1l[t] = __uint_as_float(f2tf(v - hif));
}

// ---------------- GEMM1 (3xTF32 MMA): h1h = x @ W1, fused alpha1 ----------------
__global__ __launch_bounds__(128) void k_gemm1_tc(const float* __restrict__ x,
                                                  const float* __restrict__ as1,
                                                  const float* __restrict__ ad1) {
    __shared__ float As[64][36];
    __shared__ union {
        struct {
            float Wh[32][132];
            float Wl[32][132];
        } w;
        __half Hs[64][144];
    } U;
    __shared__ unsigned salmax[8];
    int t = threadIdx.x;
    int lane = t & 31, w = t >> 5;
    int g = lane >> 2, tg = lane & 3;
    int n0 = blockIdx.x * 64;
    if (t < 8) salmax[t] = 0u;

    float acc[16][4];
#pragma unroll
    for (int nt = 0; nt < 16; nt++)
#pragma unroll
        for (int i = 0; i < 4; i++) acc[nt][i] = 0.f;

    for (int k0 = 0; k0 < 128; k0 += 32) {
#pragma unroll
        for (int i = 0; i < 4; i++) {
            int f = t + i * 128;
            int r = f >> 3, c4 = f & 7;
            int nn = n0 + r;
            if (nn >= NN) nn = NN - 1;
            float4 v = *(const float4*)&x[(size_t)nn * 128 + k0 + c4 * 4];
            *(float4*)&As[r][c4 * 4] = v;
        }
#pragma unroll
        for (int i = 0; i < 8; i++) {
            int f = t + i * 128;
            int kr = f >> 5, c4 = f & 31;
            *(float4*)&U.w.Wh[kr][c4 * 4] = *(const float4*)&g_W1h[(size_t)(k0 + kr) * 128 + c4 * 4];
            *(float4*)&U.w.Wl[kr][c4 * 4] = *(const float4*)&g_W1l[(size_t)(k0 + kr) * 128 + c4 * 4];
        }
        __syncthreads();
#pragma unroll
        for (int k8 = 0; k8 < 4; k8++) {
            float a0 = As[w * 16 + g][k8 * 8 + tg];
            float a1 = As[w * 16 + g + 8][k8 * 8 + tg];
            float a2 = As[w * 16 + g][k8 * 8 + tg + 4];
            float a3 = As[w * 16 + g + 8][k8 * 8 + tg + 4];
            unsigned ah[4], al[4];
            ah[0] = f2tf(a0);
            ah[1] = f2tf(a1);
            ah[2] = f2tf(a2);
            ah[3] = f2tf(a3);
            al[0] = f2tf(a0 - __uint_as_float(ah[0]));
            al[1] = f2tf(a1 - __uint_as_float(ah[1]));
            al[2] = f2tf(a2 - __uint_as_float(ah[2]));
            al[3] = f2tf(a3 - __uint_as_float(ah[3]));
#pragma unroll
            for (int nt = 0; nt < 16; nt++) {
                unsigned bh0 = __float_as_uint(U.w.Wh[k8 * 8 + tg][nt * 8 + g]);
                unsigned bh1 = __float_as_uint(U.w.Wh[k8 * 8 + tg + 4][nt * 8 + g]);
                unsigned bl0 = __float_as_uint(U.w.Wl[k8 * 8 + tg][nt * 8 + g]);
                unsigned bl1 = __float_as_uint(U.w.Wl[k8 * 8 + tg + 4][nt * 8 + g]);
                mma_tf32(acc[nt], ah, bh0, bh1);
                mma_tf32(acc[nt], ah, bl0, bl1);
                mma_tf32(acc[nt], al, bh0, bh1);
            }
        }
        __syncthreads();
    }

#pragma unroll
    for (int nt = 0; nt < 16; nt++) {
        int col = nt * 8 + 2 * tg;
        *(__half2*)&U.Hs[w * 16 + g][col] = __float22half2_rn(make_float2(acc[nt][0], acc[nt][1]));
        *(__half2*)&U.Hs[w * 16 + g + 8][col] = __float22half2_rn(make_float2(acc[nt][2], acc[nt][3]));
    }

    int r0 = n0 + w * 16 + g;
    int r1 = r0 + 8;
#pragma unroll
    for (int h = 0; h < 8; h++) {
        float s0 = 0.f, d0 = 0.f, s1 = 0.f, d1 = 0.f;
#pragma unroll
        for (int q = 0; q < 2; q++) {
            int nt = 2 * h + q;
            int col = nt * 8 + 2 * tg;
            float wa0 = as1[col], wa1 = as1[col + 1];
            float wd0 = ad1[col], wd1 = ad1[col + 1];
            s0 += acc[nt][0] * wa0 + acc[nt][1] * wa1;
            d0 += acc[nt][0] * wd0 + acc[nt][1] * wd1;
            s1 += acc[nt][2] * wa0 + acc[nt][3] * wa1;
            d1 += acc[nt][2] * wd0 + acc[nt][3] * wd1;
        }
        s0 += __shfl_xor_sync(FULLMASK, s0, 1);
        s0 += __shfl_xor_sync(FULLMASK, s0, 2);
        d0 += __shfl_xor_sync(FULLMASK, d0, 1);
        d0 += __shfl_xor_sync(FULLMASK, d0, 2);
        s1 += __shfl_xor_sync(FULLMASK, s1, 1);
        s1 += __shfl_xor_sync(FULLMASK, s1, 2);
        d1 += __shfl_xor_sync(FULLMASK, d1, 1);
        d1 += __shfl_xor_sync(FULLMASK, d1, 2);
        if (tg == 0) {
            if (r0 < NN) {
                g_al1[r0 * 8 + h] = s0;
                g_ar1[r0 * 8 + h] = d0;
                atomicMax(&salmax[h], fkey(s0));
            }
            if (r1 < NN) {
                g_al1[r1 * 8 + h] = s1;
                g_ar1[r1 * 8 + h] = d1;
                atomicMax(&salmax[h], fkey(s1));
            }
        }
    }
    __syncthreads();

    {
        int r = t >> 1;
        int row = n0 + r;
        int ch = (t & 1) * 64;
        if (row < NN) {
            uint4 buf[8];
#pragma unroll
            for (int i = 0; i < 8; i++) buf[i] = *(uint4*)&U.Hs[r][ch + i * 8];
#pragma unroll
            for (int i = 0; i < 8; i++) *(uint4*)&g_h1h[(size_t)row * 128 + ch + i * 8] = buf[i];
        }
    }
    if (t < 8) atomicMax(&g_almax1[t], salmax[t]);
}

// ---------------- edge1: warp/dst, unroll-4, half gather rows ----------------
__global__ __launch_bounds__(256) void k_edge1(const float* __restrict__ b1) {
    int gw = (blockIdx.x * blockDim.x + threadIdx.x) >> 5;
    int lane = threadIdx.x & 31;
    if (gw >= NN) return;
    int n = gw;
    int beg = g_rs[n], deg = g_rs[n + 1] - beg;
    int head = lane >> 2;
    float ar_h = g_ar1[n * 8 + head];
    float m = lrelu(funkey2(g_almax1[head]) + ar_h);

    float4 acc = make_float4(0.f, 0.f, 0.f, 0.f);
    float den = 0.f;
    const uint2* hp = (const uint2*)g_h1h;
    const int* cp = g_csr + beg;
    int j = 0;
    for (; j + 3 < deg; j += 4) {
        int s0 = cp[j], s1 = cp[j + 1], s2 = cp[j + 2], s3 = cp[j + 3];
        float a0 = g_al1[s0 * 8 + head];
        float a1 = g_al1[s1 * 8 + head];
        float a2 = g_al1[s2 * 8 + head];
        float a3 = g_al1[s3 * 8 + head];
        uint2 r0 = hp[(size_t)s0 * 32 + lane];
        uint2 r1 = hp[(size_t)s1 * 32 + lane];
        uint2 r2 = hp[(size_t)s2 * 32 + lane];
        uint2 r3 = hp[(size_t)s3 * 32 + lane];
        float p0 = __expf(lrelu(a0 + ar_h) - m);
        float p1 = __expf(lrelu(a1 + ar_h) - m);
        float p2 = __expf(lrelu(a2 + ar_h) - m);
        float p3 = __expf(lrelu(a3 + ar_h) - m);
        float4 h0 = h2f4(r0), h1v = h2f4(r1), h2v = h2f4(r2), h3v = h2f4(r3);
        den += (p0 + p1) + (p2 + p3);
        acc.x += p0 * h0.x + p1 * h1v.x + p2 * h2v.x + p3 * h3v.x;
        acc.y += p0 * h0.y + p1 * h1v.y + p2 * h2v.y + p3 * h3v.y;
        acc.z += p0 * h0.z + p1 * h1v.z + p2 * h2v.z + p3 * h3v.z;
        acc.w += p0 * h0.w + p1 * h1v.w + p2 * h2v.w + p3 * h3v.w;
    }
    for (; j < deg; j++) {
        int s0 = cp[j];
        float p0 = __expf(lrelu(g_al1[s0 * 8 + head] + ar_h) - m);
        float4 h0 = h2f4(hp[(size_t)s0 * 32 + lane]);
        den += p0;
        acc.x += p0 * h0.x;
        acc.y += p0 * h0.y;
        acc.z += p0 * h0.z;
        acc.w += p0 * h0.w;
    }
    float inv = (deg > 0) ? 1.0f / den : 0.0f;
    float4 bb = ((const float4*)b1)[lane];
    float4 o;
    o.x = acc.x * inv + bb.x;
    o.y = acc.y * inv + bb.y;
    o.z = acc.z * inv + bb.z;
    o.w = acc.w * inv + bb.w;
    o.x = o.x > 0.f ? o.x : (__expf(o.x) - 1.f);
    o.y = o.y > 0.f ? o.y : (__expf(o.y) - 1.f);
    o.z = o.z > 0.f ? o.z : (__expf(o.z) - 1.f);
    o.w = o.w > 0.f ? o.w : (__expf(o.w) - 1.f);
    ((float4*)g_hA)[(size_t)n * 32 + lane] = o;
    ((uint2*)g_hAh)[(size_t)n * 32 + lane] = f4h2(o);
}

// ---------------- alpha2 + almax2 tracking (separate, streaming, fp32) ----------------
__global__ __launch_bounds__(256) void k_alpha2() {
    __shared__ unsigned smax[8];
    int t = threadIdx.x;
    if (t < 8) smax[t] = 0u;
    __syncthreads();
    int wid = (blockIdx.x * blockDim.x + t) >> 5;
    int lane = t & 31;
    int nwarp = (gridDim.x * blockDim.x) >> 5;
    float ws[4][8], wd[4][8];
#pragma unroll
    for (int j = 0; j < 4; j++) {
        int k = lane * 4 + j;
#pragma unroll
        for (int h = 0; h < 8; h++) {
            ws[j][h] = g_wsrc[k * 8 + h];
            wd[j][h] = g_wdst[k * 8 + h];
        }
    }
    float lmax[8];
#pragma unroll
    for (int h = 0; h < 8; h++) lmax[h] = -1e30f;
    for (int n = wid; n < NN; n += nwarp) {
        float4 hv = ((const float4*)g_hA)[(size_t)n * 32 + lane];
        float hvv[4] = {hv.x, hv.y, hv.z, hv.w};
        float as[8], ad[8];
#pragma unroll
        for (int h = 0; h < 8; h++) {
            as[h] = 0.f;
            ad[h] = 0.f;
        }
#pragma unroll
        for (int j = 0; j < 4; j++)
#pragma unroll
            for (int h = 0; h < 8; h++) {
                as[h] += hvv[j] * ws[j][h];
                ad[h] += hvv[j] * wd[j][h];
            }
#pragma unroll
        for (int h = 0; h < 8; h++) {
#pragma unroll
            for (int o = 16; o; o >>= 1) {
                as[h] += __shfl_xor_sync(FULLMASK, as[h], o);
                ad[h] += __shfl_xor_sync(FULLMASK, ad[h], o);
            }
        }
        if (lane == 0) {
#pragma unroll
            for (int h = 0; h < 8; h++) {
                g_al2[n * 8 + h] = as[h];
                g_ar2[n * 8 + h] = ad[h];
                lmax[h] = fmaxf(lmax[h], as[h]);
            }
        }
    }
    if (lane == 0) {
#pragma unroll
        for (int h = 0; h < 8; h++) atomicMax(&smax[h], fkey(lmax[h]));
    }
    __syncthreads();
    if (t < 8) atomicMax(&g_almax2[t], smax[t]);
}

// ---------------- edge2 TENSOR v3: warp/node, coalesced gather, uniform shfl ----------------
__global__ __launch_bounds__(256) void k_edge2_tc() {
    __shared__ __half tile[8][16][136];
    int t = threadIdx.x;
    int wid = t >> 5, lane = t & 31;
    int g = lane >> 2, tg = lane & 3;
    int n = blockIdx.x * 8 + wid;
    if (n >= NN) return;
    int beg = g_rs[n], deg = g_rs[n + 1] - beg;
    __half* wtile = &tile[wid][0][0];

    if (deg == 0) {
        uint2* outp = (uint2*)(g_aggh + (size_t)n * 1024);
        uint2 z = make_uint2(0u, 0u);
        for (int i = lane; i < 256; i += 32) outp[i] = z;
        return;
    }

    float ar_g = g_ar2[n * 8 + g];
    float m_g = lrelu(funkey2(g_almax2[g]) + ar_g);
    const int* cp = g_csr + beg;

    float c[8][4];
#pragma unroll
    for (int f = 0; f < 8; f++) {
        c[f][0] = 0.f; c[f][1] = 0.f; c[f][2] = 0.f; c[f][3] = 0.f;
    }
    float den = 0.f;

    int arow = (lane & 7) | ((lane >> 1) & 8);
    int acol = lane & 8;
    unsigned abase = (unsigned)__cvta_generic_to_shared(&tile[wid][arow][acol]);

    for (int j0 = 0; j0 < deg; j0 += 16) {
        __syncwarp();
        // preload chunk's 16 csr indices into lanes 0..15 (dup 16..31), clamped
        int ej = j0 + (lane & 15);
        if (ej >= deg) ej = deg - 1;
        int idx16 = cp[ej];
        // coalesced gather: whole warp loads one 256B row per iteration
#pragma unroll
        for (int r = 0; r < 16; r++) {
            int src = __shfl_sync(FULLMASK, idx16, r);
            uint2 v = *(const uint2*)(g_hAh + (size_t)src * 128 + lane * 4);
            *(uint2*)&tile[wid][r][lane * 4] = v;
        }
        // B fragment: head g, edges tg*2, tg*2+1, tg*2+8, tg*2+9
        // NOTE: shfl is UNCONDITIONAL (uniform participation); only p is masked.
        float pv[4];
#pragma unroll
        for (int q = 0; q < 4; q++) {
            int eo = (q & 1) + ((q >> 1) << 3) + tg * 2;
            int s = __shfl_sync(FULLMASK, idx16, eo);  // always executed, s valid (clamped)
            float p = 0.f;
            if (j0 + eo < deg) {
                p = __expf(lrelu(g_al2[s * 8 + g] + ar_g) - m_g);
            }
            pv[q] = p;
        }
        __half2 b0h = __floats2half2_rn(pv[0], pv[1]);
        __half2 b1h = __floats2half2_rn(pv[2], pv[3]);
        float2 f0 = __half22float2(b0h), f1 = __half22float2(b1h);
        den += (f0.x + f0.y) + (f1.x + f1.y);
        unsigned b0 = *(unsigned*)&b0h, b1 = *(unsigned*)&b1h;
        __syncwarp();
#pragma unroll
        for (int f = 0; f < 8; f++) {
            unsigned a0, a1, a2, a3;
            ldsm4t(a0, a1, a2, a3, abase + f * 32);
            mma_f16(c[f], a0, a1, a2, a3, b0, b1);
        }
    }

    den += __shfl_xor_sync(FULLMASK, den, 1);
    den += __shfl_xor_sync(FULLMASK, den, 2);
    float d0 = __shfl_sync(FULLMASK, den, (2 * tg) * 4);
    float d1 = __shfl_sync(FULLMASK, den, (2 * tg + 1) * 4);
    float iv0 = (d0 > 0.f) ? 1.f / d0 : 0.f;
    float iv1 = (d1 > 0.f) ? 1.f / d1 : 0.f;

    __syncwarp();
#pragma unroll
    for (int f = 0; f < 8; f++) {
        wtile[(2 * tg) * 136 + f * 16 + g] = __float2half_rn(c[f][0] * iv0);
        wtile[(2 * tg + 1) * 136 + f * 16 + g] = __float2half_rn(c[f][1] * iv1);
        wtile[(2 * tg) * 136 + f * 16 + g + 8] = __float2half_rn(c[f][2] * iv0);
        wtile[(2 * tg + 1) * 136 + f * 16 + g + 8] = __float2half_rn(c[f][3] * iv1);
    }
    __syncwarp();
    uint2* outp = (uint2*)(g_aggh + (size_t)n * 1024);
#pragma unroll
    for (int h = 0; h < 8; h++) {
        uint2 v = *(uint2*)&wtile[h * 136 + lane * 4];
        outp[h * 32 + lane] = v;
    }
}

// ---------------- GEMM3: out = aggh[N,1024] @ Wbig[1024,40] + b2 (2xTF32 MMA) ----------------
__global__ __launch_bounds__(128) void k_gemm3_tc(const float* __restrict__ b2,
                                                  float* __restrict__ out) {
    __shared__ float As[64][36];
    __shared__ float Bh[32][40];
    __shared__ float Bl[32][40];
    int t = threadIdx.x;
    int lane = t & 31, w = t >> 5;
    int g = lane >> 2, tg = lane & 3;
    int n0 = blockIdx.x * 64;

    float acc[5][4];
#pragma unroll
    for (int nt = 0; nt < 5; nt++)
#pragma unroll
        for (int i = 0; i < 4; i++) acc[nt][i] = 0.f;

    for (int k0 = 0; k0 < 1024; k0 += 32) {
#pragma unroll
        for (int i = 0; i < 4; i++) {
            int f = t + i * 128;
            int r = f >> 3, c4 = f & 7;
            int nn = n0 + r;
            if (nn >= NN) nn = NN - 1;
            uint2 v = *(const uint2*)&g_aggh[(size_t)nn * 1024 + k0 + c4 * 4];
            *(float4*)&As[r][c4 * 4] = h2f4(v);
        }
#pragma unroll
        for (int i = 0; i < 10; i++) {
            int f = t + i * 128;
            int k = f / 40, c = f % 40;
            Bh[k][c] = g_Wb_hi[(size_t)(k0 + k) * 40 + c];
            Bl[k][c] = g_Wb_lo[(size_t)(k0 + k) * 40 + c];
        }
        __syncthreads();
#pragma unroll
        for (int k8 = 0; k8 < 4; k8++) {
            unsigned ah[4];
            ah[0] = f2tf(As[w * 16 + g][k8 * 8 + tg]);
            ah[1] = f2tf(As[w * 16 + g + 8][k8 * 8 + tg]);
            ah[2] = f2tf(As[w * 16 + g][k8 * 8 + tg + 4]);
            ah[3] = f2tf(As[w * 16 + g + 8][k8 * 8 + tg + 4]);
#pragma unroll
            for (int nt = 0; nt < 5; nt++) {
                unsigned bh0 = __float_as_uint(Bh[k8 * 8 + tg][nt * 8 + g]);
                unsigned bh1 = __float_as_uint(Bh[k8 * 8 + tg + 4][nt * 8 + g]);
                unsigned bl0 = __float_as_uint(Bl[k8 * 8 + tg][nt * 8 + g]);
                unsigned bl1 = __float_as_uint(Bl[k8 * 8 + tg + 4][nt * 8 + g]);
                mma_tf32(acc[nt], ah, bh0, bh1);
                mma_tf32(acc[nt], ah, bl0, bl1);
            }
        }
        __syncthreads();
    }

#pragma unroll
    for (int nt = 0; nt < 5; nt++) {
        int col = nt * 8 + 2 * tg;
        float bx = b2[col], by = b2[col + 1];
        int r0 = n0 + w * 16 + g;
        if (r0 < NN) {
            *(float2*)&out[(size_t)r0 * 40 + col] = make_float2(acc[nt][0] + bx, acc[nt][1] + by);
        }
        int r1 = r0 + 8;
        if (r1 < NN) {
            *(float2*)&out[(size_t)r1 * 40 + col] = make_float2(acc[nt][2] + bx, acc[nt][3] + by);
        }
    }
}

// ---------------- host launcher ----------------
extern "C" void kernel_launch(void* const* d_in, const int* in_sizes, int n_in,
                              void* d_out, int out_size) {
    const float* x = (const float*)d_in[0];
    const void* ei = d_in[1];
    const float* W1 = (const float*)d_in[2];
    const float* as1 = (const float*)d_in[3];
    const float* ad1 = (const float*)d_in[4];
    const float* b1 = (const float*)d_in[5];
    const float* W2 = (const float*)d_in[6];
    const float* as2 = (const float*)d_in[7];
    const float* ad2 = (const float*)d_in[8];
    const float* b2 = (const float*)d_in[9];
    float* out = (float*)d_out;

    k_init<<<98, 1024>>>((const long long*)ei);
    k_hist<<<(NE / 4 + 255) / 256, 256>>>(ei);
    k_scan1<<<25, 1024>>>();
    k_scan2<<<1, 32>>>(25);
    k_scan3<<<25, 1024>>>();
    k_fill<<<(NE / 4 + 255) / 256, 256>>>(ei);
    k_prep_w1<<<64, 256>>>(W1);
    k_gemm1_tc<<<(NN + 63) / 64, 128>>>(x, as1, ad1);
    k_edge1<<<(NN * 32 + 255) / 256, 256>>>(b1);
    k_prep_eff<<<4, 256>>>(W2, as2, ad2);
    k_prep_wbig<<<160, 256>>>(W2);
    k_alpha2<<<592, 256>>>();
    k_edge2_tc<<<(NN + 7) / 8, 256>>>();
    k_gemm3_tc<<<(NN + 63) / 64, 128>>>(b2, out);
}